// round 8
// baseline (speedup 1.0000x reference)
#include <cuda_runtime.h>

#define RADIAL 160
#define RPB 4                          // rows per block
#define ROW_F (RADIAL * 3)             // 480 scalars per row
#define ROW_F4 (ROW_F / 4)             // 120 float4 per row
#define NTHREADS (RPB * ROW_F4)        // 480 threads
#define LPAD 20                        // left zero pad (scalars), mult of 4
#define RPAD 20                        // right zero pad (scalars)
#define SROWF (LPAD + ROW_F + RPAD)    // 520 scalars per stored row
#define SROWF4 (SROWF / 4)             // 130 float4 per stored row

struct Params {
    float dt_offset;
    float dt_persist;
    float k, cc;
    float amount;
    float w[5];
    int   D;
    int   edge;
    int   G;       // uniform float4 window base offset: bf = r4 + G
    int   p;       // uniform alignment phase 0..3
};

__device__ Params g_params;
__device__ float g_coefT[4 * ROW_F];   // SoA: g_coefT[d*480 + s] = tap d of scalar s

__global__ void prep_kernel(const float* __restrict__ offset,
                            const float* __restrict__ persistence,
                            const float* __restrict__ diffusion01,
                            const float* __restrict__ dt_seconds,
                            const float* __restrict__ amount01,
                            const float* __restrict__ spread01) {
    const int s = threadIdx.x;           // 0..479 (one per output scalar)

    float dt = fminf(fmaxf(*dt_seconds, 0.0f), 0.05f);
    float dt_scale = dt * 60.0f;
    float off = (*offset) * dt_scale;
    float P   = powf(*persistence, dt_scale);
    float k   = 0.15f * (*diffusion01);
    float cc  = 1.0f - 2.0f * k;
    int   D   = (int)floorf(off);

    // Edge check over bins: does floor(i+off) deviate from i+D?
    int myedge = 0;
    if (s < RADIAL) {
        float npi = (float)s + off;
        bool validi = (npi >= 0.0f) && (npi < (float)(RADIAL - 1));
        int lii = min(max((int)floorf(npi), 0), RADIAL - 2);
        myedge = (validi && (lii != s + D)) ? 1 : 0;
    }
    int edge = __syncthreads_or(myedge);

    if (s == 0) {
        g_params.dt_offset  = off;
        g_params.dt_persist = P;
        g_params.k  = k;
        g_params.cc = cc;
        g_params.D  = D;
        g_params.edge = edge;
        g_params.amount = fminf(fmaxf(*amount01, 0.0f), 1.0f);
        float spread = fminf(fmaxf(*spread01, 0.0f), 1.0f);
        float tight  = 1.0f - spread;
        g_params.w[0] = 0.5f + 0.4f * tight;
        g_params.w[1] = 0.2f * spread + 0.05f;
        g_params.w[2] = 0.12f * spread;
        g_params.w[3] = 0.06f * spread;
        g_params.w[4] = 0.02f * spread;
        // Window geometry: scalar of (r4=0, e=0, d=0) tap = LPAD - 3(D+2)
        int b0 = LPAD - 3 * (D + 2);
        int p  = ((b0 % 4) + 4) % 4;
        g_params.p = p;
        g_params.G = (b0 - p) / 4;       // exact (b0 - p divisible by 4)
    }

    // Fused per-bin coefficients (advect + diffuse + fade), SoA per scalar.
    const int bin = s / 3;
    float fade = 1.0f;
    if (bin >= RADIAL - 8) {
        float tt = (float)(RADIAL - 1 - bin) * 0.125f;
        fade = tt * tt;
    }
    float c[4] = {0.0f, 0.0f, 0.0f, 0.0f};
    #pragma unroll
    for (int d = 0; d < 4; d++) {
        int src = bin - D - 2 + d;
        if (src < 0 || src >= RADIAL) continue;
        float nps = (float)src + off;               // same fp ops as reference
        if (!(nps >= 0.0f && nps < (float)(RADIAL - 1))) continue;
        int   ls  = min(max((int)floorf(nps), 0), RADIAL - 2);
        float fr  = nps - (float)ls;
        float wls = (1.0f - fr) * P;
        float wrs = fr * P;
        float sb  = (ls == bin     ? wls : 0.0f) + (ls + 1 == bin     ? wrs : 0.0f);
        float sbm = 0.0f, sbp = 0.0f;
        if (bin >= 1)
            sbm = (ls == bin - 1 ? wls : 0.0f) + (ls + 1 == bin - 1 ? wrs : 0.0f);
        if (bin <= RADIAL - 2)
            sbp = (ls == bin + 1 ? wls : 0.0f) + (ls + 1 == bin + 1 ? wrs : 0.0f);
        c[d] = (cc * sb + k * (sbm + sbp)) * fade;
    }
    #pragma unroll
    for (int d = 0; d < 4; d++) g_coefT[d * ROW_F + s] = c[d];
}

// Register component selector: scalar J (0..15) of the window {V0,V1,V2,V3}.
template<int J>
__device__ __forceinline__ float getc(const float4 V0, const float4 V1,
                                      const float4 V2, const float4 V3) {
    if constexpr      (J == 0)  return V0.x;
    else if constexpr (J == 1)  return V0.y;
    else if constexpr (J == 2)  return V0.z;
    else if constexpr (J == 3)  return V0.w;
    else if constexpr (J == 4)  return V1.x;
    else if constexpr (J == 5)  return V1.y;
    else if constexpr (J == 6)  return V1.z;
    else if constexpr (J == 7)  return V1.w;
    else if constexpr (J == 8)  return V2.x;
    else if constexpr (J == 9)  return V2.y;
    else if constexpr (J == 10) return V2.z;
    else if constexpr (J == 11) return V2.w;
    else if constexpr (J == 12) return V3.x;
    else if constexpr (J == 13) return V3.y;
    else if constexpr (J == 14) return V3.z;
    else                        return V3.w;
}

// out.e = sum_d Cd.e * W[P + e + 3d]   (all register ops, fully inlined)
template<int P>
__device__ __forceinline__ float4 apply_taps(const float4 V0, const float4 V1,
                                             const float4 V2, const float4 V3,
                                             const float4 C0, const float4 C1,
                                             const float4 C2, const float4 C3) {
    float4 o;
    o.x = C0.x * getc<P + 0>(V0,V1,V2,V3) + C1.x * getc<P + 3>(V0,V1,V2,V3)
        + C2.x * getc<P + 6>(V0,V1,V2,V3) + C3.x * getc<P + 9>(V0,V1,V2,V3);
    o.y = C0.y * getc<P + 1>(V0,V1,V2,V3) + C1.y * getc<P + 4>(V0,V1,V2,V3)
        + C2.y * getc<P + 7>(V0,V1,V2,V3) + C3.y * getc<P + 10>(V0,V1,V2,V3);
    o.z = C0.z * getc<P + 2>(V0,V1,V2,V3) + C1.z * getc<P + 5>(V0,V1,V2,V3)
        + C2.z * getc<P + 8>(V0,V1,V2,V3) + C3.z * getc<P + 11>(V0,V1,V2,V3);
    o.w = C0.w * getc<P + 3>(V0,V1,V2,V3) + C1.w * getc<P + 6>(V0,V1,V2,V3)
        + C2.w * getc<P + 9>(V0,V1,V2,V3) + C3.w * getc<P + 12>(V0,V1,V2,V3);
    return o;
}

__global__ __launch_bounds__(NTHREADS, 3)
void beat_pulse_kernel(const float* __restrict__ history,
                       const float* __restrict__ color_rgb,
                       float* __restrict__ out) {
    __shared__ float s1[RPB * SROWF];      // clipped history w/ zero pads
    __shared__ float scoef[4 * ROW_F];     // SoA coef planes (7.5 KB)

    const int t = threadIdx.x;
    const long long base_row = (long long)blockIdx.x * RPB;
    const int row = t / ROW_F4;
    const int r4  = t - row * ROW_F4;      // float4 index within row

    // ---- stage coef planes into SMEM (coalesced, once per block) ----
    ((float4*)scoef)[t] = ((const float4*)g_coefT)[t];

    // ---- zero pads: 10 float4 per row ----
    if (t < RPB * 10) {
        int r = t / 10;
        int j = t - r * 10;
        int f4 = (j < 5) ? j : (SROWF4 - 5 + (j - 5));
        ((float4*)&s1[r * SROWF])[f4] = make_float4(0.f, 0.f, 0.f, 0.f);
    }

    // ---- Phase 1: coalesced float4 load + inject + clip01 -> SMEM ----
    {
        const float* gin = history + (base_row + row) * ROW_F;
        float4 v = ((const float4*)gin)[r4];
        float vals[4] = {v.x, v.y, v.z, v.w};
        if (r4 < 4) {                       // inject region: scalars [0,15)
            long long b = base_row + row;
            float amount = g_params.amount;
            float en[3];
            en[0] = color_rgb[b * 3 + 0] * amount;
            en[1] = color_rgb[b * 3 + 1] * amount;
            en[2] = color_rgb[b * 3 + 2] * amount;
            #pragma unroll
            for (int e = 0; e < 4; e++) {
                int sidx = r4 * 4 + e;
                int bin  = sidx / 3;
                int ch   = sidx - bin * 3;
                if (bin < 5) vals[e] += en[ch] * g_params.w[bin];
            }
        }
        #pragma unroll
        for (int e = 0; e < 4; e++) vals[e] = fminf(fmaxf(vals[e], 0.0f), 1.0f);
        float4 o; o.x = vals[0]; o.y = vals[1]; o.z = vals[2]; o.w = vals[3];
        ((float4*)&s1[row * SROWF])[(LPAD / 4) + r4] = o;
    }
    __syncthreads();

    if (!g_params.edge) {
        // ---- Fast path: fused 4-tap banded operator, all in registers ----
        int bf = r4 + g_params.G;
        bf = min(max(bf, 0), SROWF4 - 4);       // clamp => all coefs zero there
        const float4* S4 = (const float4*)&s1[row * SROWF];
        float4 V0 = S4[bf + 0];
        float4 V1 = S4[bf + 1];
        float4 V2 = S4[bf + 2];
        float4 V3 = S4[bf + 3];
        // conflict-free stride-16B plane reads
        float4 C0 = ((const float4*)&scoef[0 * ROW_F])[r4];
        float4 C1 = ((const float4*)&scoef[1 * ROW_F])[r4];
        float4 C2 = ((const float4*)&scoef[2 * ROW_F])[r4];
        float4 C3 = ((const float4*)&scoef[3 * ROW_F])[r4];

        float4 o;
        switch (g_params.p) {                   // uniform branch
            case 0:  o = apply_taps<0>(V0,V1,V2,V3,C0,C1,C2,C3); break;
            case 1:  o = apply_taps<1>(V0,V1,V2,V3,C0,C1,C2,C3); break;
            case 2:  o = apply_taps<2>(V0,V1,V2,V3,C0,C1,C2,C3); break;
            default: o = apply_taps<3>(V0,V1,V2,V3,C0,C1,C2,C3); break;
        }
        ((float4*)(out + (base_row + row) * ROW_F))[r4] = o;
    } else {
        // ---- Generic fallback (never taken for bench params) ----
        const float off = g_params.dt_offset;
        const float P   = g_params.dt_persist;
        const int   D   = g_params.D;

        float adv[2][3];
        int nloc = 0;
        for (int bb = t; bb < RPB * RADIAL; bb += NTHREADS, nloc++) {
            int rr  = bb / RADIAL;
            int bin = bb - rr * RADIAL;
            const float* s1r = s1 + rr * SROWF + LPAD;
            float wk0 = 0.0f, wk1 = 0.0f, wk2 = 0.0f;
            #pragma unroll
            for (int d = -2; d <= 1; d++) {
                int i = bin - D + d;
                float np = (float)i + off;
                float lf = floorf(np);
                int   li = (int)lf;
                float fr = np - lf;
                bool vs = (i >= 0) & (i < RADIAL) & (np >= 0.0f) & (np < (float)(RADIAL - 1));
                float wl = (vs && li == bin)     ? (1.0f - fr) * P : 0.0f;
                float wr = (vs && li == bin - 1) ? fr * P          : 0.0f;
                float w = wl + wr;
                int a = min(max(i, 0), RADIAL - 1) * 3;
                wk0 += w * s1r[a + 0];
                wk1 += w * s1r[a + 1];
                wk2 += w * s1r[a + 2];
            }
            adv[nloc][0] = wk0; adv[nloc][1] = wk1; adv[nloc][2] = wk2;
        }
        __syncthreads();
        nloc = 0;
        for (int bb = t; bb < RPB * RADIAL; bb += NTHREADS, nloc++) {
            int rr  = bb / RADIAL;
            int bin = bb - rr * RADIAL;
            float* s1r = s1 + rr * SROWF + LPAD;
            s1r[bin * 3 + 0] = adv[nloc][0];
            s1r[bin * 3 + 1] = adv[nloc][1];
            s1r[bin * 3 + 2] = adv[nloc][2];
        }
        __syncthreads();
        const float k  = g_params.k;
        const float cc = g_params.cc;
        for (int bb = t; bb < RPB * RADIAL; bb += NTHREADS) {
            int rr  = bb / RADIAL;
            int bin = bb - rr * RADIAL;
            const float* s1r = s1 + rr * SROWF + LPAD;
            float fade = 1.0f;
            if (bin >= RADIAL - 8) {
                float tt = (float)(RADIAL - 1 - bin) * 0.125f;
                fade = tt * tt;
            }
            float* gout = out + (base_row + rr) * ROW_F + bin * 3;
            #pragma unroll
            for (int c = 0; c < 3; c++) {
                float xc = s1r[bin * 3 + c];
                float xm = s1r[(bin - 1) * 3 + c];
                float xp = s1r[(bin + 1) * 3 + c];
                gout[c] = (cc * xc + k * xm + k * xp) * fade;
            }
        }
    }
}

extern "C" void kernel_launch(void* const* d_in, const int* in_sizes, int n_in,
                              void* d_out, int out_size) {
    const float* history     = (const float*)d_in[0];
    const float* color_rgb   = (const float*)d_in[1];
    const float* offset      = (const float*)d_in[2];
    const float* persistence = (const float*)d_in[3];
    const float* diffusion01 = (const float*)d_in[4];
    const float* dt_seconds  = (const float*)d_in[5];
    const float* amount01    = (const float*)d_in[6];
    const float* spread01    = (const float*)d_in[7];
    float* out = (float*)d_out;

    int B = in_sizes[0] / ROW_F;
    int grid = (B + RPB - 1) / RPB;

    prep_kernel<<<1, ROW_F>>>(offset, persistence, diffusion01, dt_seconds,
                              amount01, spread01);
    beat_pulse_kernel<<<grid, NTHREADS>>>(history, color_rgb, out);
}

// round 9
// speedup vs baseline: 1.0435x; 1.0435x over previous
#include <cuda_runtime.h>

#define RADIAL 160
#define ROW_F 480                 // scalars per row
#define ROW_F4 120                // float4 per row
#define NT 256                    // hot kernel block size

struct Params {
    float dt_offset;
    float dt_persist;
    float k, cc;
    float amount;
    float w[5];
    int   D;
    int   edge;
    int   G2;      // window f4 offset (global, row-relative): wf4 = r4 + G2
    int   p;       // alignment phase 0..3
};

__device__ Params g_params;
__device__ float g_coefT[4 * ROW_F];   // SoA planes: g_coefT[d*480 + s]

__global__ void prep_kernel(const float* __restrict__ offset,
                            const float* __restrict__ persistence,
                            const float* __restrict__ diffusion01,
                            const float* __restrict__ dt_seconds,
                            const float* __restrict__ amount01,
                            const float* __restrict__ spread01) {
    const int s = threadIdx.x;           // 0..479

    float dt = fminf(fmaxf(*dt_seconds, 0.0f), 0.05f);
    float dt_scale = dt * 60.0f;
    float off = (*offset) * dt_scale;
    float P   = powf(*persistence, dt_scale);
    float k   = 0.15f * (*diffusion01);
    float cc  = 1.0f - 2.0f * k;
    int   D   = (int)floorf(off);

    int myedge = 0;
    if (s < RADIAL) {
        float npi = (float)s + off;
        bool validi = (npi >= 0.0f) && (npi < (float)(RADIAL - 1));
        int lii = min(max((int)floorf(npi), 0), RADIAL - 2);
        myedge = (validi && (lii != s + D)) ? 1 : 0;
    }
    int edge = __syncthreads_or(myedge);

    if (s == 0) {
        g_params.dt_offset  = off;
        g_params.dt_persist = P;
        g_params.k  = k;
        g_params.cc = cc;
        g_params.D  = D;
        g_params.edge = edge;
        g_params.amount = fminf(fmaxf(*amount01, 0.0f), 1.0f);
        float spread = fminf(fmaxf(*spread01, 0.0f), 1.0f);
        float tight  = 1.0f - spread;
        g_params.w[0] = 0.5f + 0.4f * tight;
        g_params.w[1] = 0.2f * spread + 0.05f;
        g_params.w[2] = 0.12f * spread;
        g_params.w[3] = 0.06f * spread;
        g_params.w[4] = 0.02f * spread;
        // Window geometry (row-relative scalars): first tap of scalar 4*r4 is
        // 4*r4 + b0, b0 = -3*(D+2).  p = misalignment, G2 = aligned f4 shift.
        int b0 = -3 * (D + 2);
        int p  = ((b0 % 4) + 4) % 4;
        g_params.p  = p;
        g_params.G2 = (b0 - p) / 4;
    }

    // Fused per-bin coefficients (advect + diffuse + fade), SoA per scalar.
    const int bin = s / 3;
    float fade = 1.0f;
    if (bin >= RADIAL - 8) {
        float tt = (float)(RADIAL - 1 - bin) * 0.125f;
        fade = tt * tt;
    }
    float c[4] = {0.0f, 0.0f, 0.0f, 0.0f};
    #pragma unroll
    for (int d = 0; d < 4; d++) {
        int src = bin - D - 2 + d;
        if (src < 0 || src >= RADIAL) continue;
        float nps = (float)src + off;               // same fp ops as reference
        if (!(nps >= 0.0f && nps < (float)(RADIAL - 1))) continue;
        int   ls  = min(max((int)floorf(nps), 0), RADIAL - 2);
        float fr  = nps - (float)ls;
        float wls = (1.0f - fr) * P;
        float wrs = fr * P;
        float sb  = (ls == bin     ? wls : 0.0f) + (ls + 1 == bin     ? wrs : 0.0f);
        float sbm = 0.0f, sbp = 0.0f;
        if (bin >= 1)
            sbm = (ls == bin - 1 ? wls : 0.0f) + (ls + 1 == bin - 1 ? wrs : 0.0f);
        if (bin <= RADIAL - 2)
            sbp = (ls == bin + 1 ? wls : 0.0f) + (ls + 1 == bin + 1 ? wrs : 0.0f);
        c[d] = (cc * sb + k * (sbm + sbp)) * fade;
    }
    #pragma unroll
    for (int d = 0; d < 4; d++) g_coefT[d * ROW_F + s] = c[d];
}

// Register component selector: scalar J (0..15) of window {V0..V3}.
template<int J>
__device__ __forceinline__ float getc(const float4 V0, const float4 V1,
                                      const float4 V2, const float4 V3) {
    if constexpr      (J == 0)  return V0.x;
    else if constexpr (J == 1)  return V0.y;
    else if constexpr (J == 2)  return V0.z;
    else if constexpr (J == 3)  return V0.w;
    else if constexpr (J == 4)  return V1.x;
    else if constexpr (J == 5)  return V1.y;
    else if constexpr (J == 6)  return V1.z;
    else if constexpr (J == 7)  return V1.w;
    else if constexpr (J == 8)  return V2.x;
    else if constexpr (J == 9)  return V2.y;
    else if constexpr (J == 10) return V2.z;
    else if constexpr (J == 11) return V2.w;
    else if constexpr (J == 12) return V3.x;
    else if constexpr (J == 13) return V3.y;
    else if constexpr (J == 14) return V3.z;
    else                        return V3.w;
}

template<int P>
__device__ __forceinline__ float4 apply_taps(const float4 V0, const float4 V1,
                                             const float4 V2, const float4 V3,
                                             const float4 C0, const float4 C1,
                                             const float4 C2, const float4 C3) {
    float4 o;
    o.x = C0.x * getc<P + 0>(V0,V1,V2,V3) + C1.x * getc<P + 3>(V0,V1,V2,V3)
        + C2.x * getc<P + 6>(V0,V1,V2,V3) + C3.x * getc<P + 9>(V0,V1,V2,V3);
    o.y = C0.y * getc<P + 1>(V0,V1,V2,V3) + C1.y * getc<P + 4>(V0,V1,V2,V3)
        + C2.y * getc<P + 7>(V0,V1,V2,V3) + C3.y * getc<P + 10>(V0,V1,V2,V3);
    o.z = C0.z * getc<P + 2>(V0,V1,V2,V3) + C1.z * getc<P + 5>(V0,V1,V2,V3)
        + C2.z * getc<P + 8>(V0,V1,V2,V3) + C3.z * getc<P + 11>(V0,V1,V2,V3);
    o.w = C0.w * getc<P + 3>(V0,V1,V2,V3) + C1.w * getc<P + 6>(V0,V1,V2,V3)
        + C2.w * getc<P + 9>(V0,V1,V2,V3) + C3.w * getc<P + 12>(V0,V1,V2,V3);
    return o;
}

__device__ __forceinline__ float4 clamp01_4(float4 v) {
    v.x = fminf(fmaxf(v.x, 0.0f), 1.0f);
    v.y = fminf(fmaxf(v.y, 0.0f), 1.0f);
    v.z = fminf(fmaxf(v.z, 0.0f), 1.0f);
    v.w = fminf(fmaxf(v.w, 0.0f), 1.0f);
    return v;
}

// Inject + clip for one (row, srcbin, ch) — used only by the generic fallback.
__device__ __forceinline__ float loadclip(const float* __restrict__ history,
                                          const float* __restrict__ color_rgb,
                                          int row, int srcbin, int ch) {
    int sb = min(max(srcbin, 0), RADIAL - 1);
    float v = history[(long long)row * ROW_F + sb * 3 + ch];
    if (sb < 5)
        v += color_rgb[row * 3 + ch] * g_params.amount * g_params.w[sb];
    return fminf(fmaxf(v, 0.0f), 1.0f);
}

__global__ __launch_bounds__(NT)
void beat_pulse_main(const float* __restrict__ history,
                     const float* __restrict__ color_rgb,
                     float* __restrict__ out, int nrows) {
    const int g = blockIdx.x * NT + threadIdx.x;     // global output f4 index
    const int total_f4 = nrows * ROW_F4;
    if (g >= total_f4) return;
    const int row = g / ROW_F4;
    const int r4  = g - row * ROW_F4;

    if (!g_params.edge) {
        // ---- pure gather: 4 overlapping window loads, coefs kill OOR taps ----
        const int base = g + g_params.G2;
        const int mx = total_f4 - 1;
        const float4* H4 = (const float4*)history;
        int a0 = min(max(base + 0, 0), mx);
        int a1 = min(max(base + 1, 0), mx);
        int a2 = min(max(base + 2, 0), mx);
        int a3 = min(max(base + 3, 0), mx);
        float4 V0 = clamp01_4(__ldg(&H4[a0]));
        float4 V1 = clamp01_4(__ldg(&H4[a1]));
        float4 V2 = clamp01_4(__ldg(&H4[a2]));
        float4 V3 = clamp01_4(__ldg(&H4[a3]));

        const float4* CT = (const float4*)g_coefT;
        float4 C0 = __ldg(&CT[(0 * ROW_F) / 4 + r4]);
        float4 C1 = __ldg(&CT[(1 * ROW_F) / 4 + r4]);
        float4 C2 = __ldg(&CT[(2 * ROW_F) / 4 + r4]);
        float4 C3 = __ldg(&CT[(3 * ROW_F) / 4 + r4]);

        float4 o;
        switch (g_params.p) {                        // uniform branch
            case 0:  o = apply_taps<0>(V0,V1,V2,V3,C0,C1,C2,C3); break;
            case 1:  o = apply_taps<1>(V0,V1,V2,V3,C0,C1,C2,C3); break;
            case 2:  o = apply_taps<2>(V0,V1,V2,V3,C0,C1,C2,C3); break;
            default: o = apply_taps<3>(V0,V1,V2,V3,C0,C1,C2,C3); break;
        }
        ((float4*)out)[g] = o;
    } else {
        // ---- generic fallback (never taken for bench params) ----
        const float off = g_params.dt_offset;
        const float P   = g_params.dt_persist;
        const float k   = g_params.k;
        const float cc  = g_params.cc;
        const int   D   = g_params.D;
        float res[4];
        #pragma unroll
        for (int e = 0; e < 4; e++) {
            int s   = 4 * r4 + e;
            int bin = s / 3;
            int ch  = s - 3 * bin;
            float adv[3];
            #pragma unroll
            for (int bo = -1; bo <= 1; bo++) {
                int bb = bin + bo;
                float a = 0.0f;
                if (bb >= 0 && bb < RADIAL) {
                    #pragma unroll
                    for (int d = -2; d <= 1; d++) {
                        int i = bb - D + d;
                        float np = (float)i + off;
                        float lf = floorf(np);
                        int   li = (int)lf;
                        float fr = np - lf;
                        bool vs = (i >= 0) & (i < RADIAL) &
                                  (np >= 0.0f) & (np < (float)(RADIAL - 1));
                        float wl = (vs && li == bb)     ? (1.0f - fr) * P : 0.0f;
                        float wr = (vs && li == bb - 1) ? fr * P          : 0.0f;
                        float w = wl + wr;
                        if (w != 0.0f)
                            a += w * loadclip(history, color_rgb, row, i, ch);
                    }
                }
                adv[bo + 1] = a;
            }
            float fade = 1.0f;
            if (bin >= RADIAL - 8) {
                float tt = (float)(RADIAL - 1 - bin) * 0.125f;
                fade = tt * tt;
            }
            res[e] = (cc * adv[1] + k * adv[0] + k * adv[2]) * fade;
        }
        float4 o; o.x = res[0]; o.y = res[1]; o.z = res[2]; o.w = res[3];
        ((float4*)out)[g] = o;
    }
}

// Recompute the <=24 inject-affected output scalars per row, exactly.
__global__ void fixup_kernel(const float* __restrict__ history,
                             const float* __restrict__ color_rgb,
                             float* __restrict__ out, int nrows) {
    if (g_params.edge) return;                       // generic path handled it
    int row = blockIdx.x * blockDim.x + threadIdx.x;
    if (row >= nrows) return;

    const int D = g_params.D;
    int blo = max(0, D - 1);
    int bhi = min(RADIAL - 1, D + 6);
    if (blo > bhi) return;

    // Sources needed: bins 0..7 (scalars 0..23), inject bins 0..4, then clip.
    const float* hr = history + (long long)row * ROW_F;
    float amount = g_params.amount;
    float en0 = color_rgb[row * 3 + 0] * amount;
    float en1 = color_rgb[row * 3 + 1] * amount;
    float en2 = color_rgb[row * 3 + 2] * amount;
    float hs[24];
    #pragma unroll
    for (int sb = 0; sb < 8; sb++) {
        float w = (sb < 5) ? g_params.w[sb] : 0.0f;
        hs[sb * 3 + 0] = fminf(fmaxf(hr[sb * 3 + 0] + en0 * w, 0.0f), 1.0f);
        hs[sb * 3 + 1] = fminf(fmaxf(hr[sb * 3 + 1] + en1 * w, 0.0f), 1.0f);
        hs[sb * 3 + 2] = fminf(fmaxf(hr[sb * 3 + 2] + en2 * w, 0.0f), 1.0f);
    }

    float* orow = out + (long long)row * ROW_F;
    for (int b = blo; b <= bhi; b++) {
        #pragma unroll
        for (int ch = 0; ch < 3; ch++) {
            float acc = 0.0f;
            #pragma unroll
            for (int d = 0; d < 4; d++) {
                int sb = b - D - 2 + d;
                if (sb >= 0 && sb < 8)
                    acc += g_coefT[d * ROW_F + b * 3 + ch] * hs[sb * 3 + ch];
            }
            orow[b * 3 + ch] = acc;
        }
    }
}

extern "C" void kernel_launch(void* const* d_in, const int* in_sizes, int n_in,
                              void* d_out, int out_size) {
    const float* history     = (const float*)d_in[0];
    const float* color_rgb   = (const float*)d_in[1];
    const float* offset      = (const float*)d_in[2];
    const float* persistence = (const float*)d_in[3];
    const float* diffusion01 = (const float*)d_in[4];
    const float* dt_seconds  = (const float*)d_in[5];
    const float* amount01    = (const float*)d_in[6];
    const float* spread01    = (const float*)d_in[7];
    float* out = (float*)d_out;

    int nrows = in_sizes[0] / ROW_F;                 // 65536
    int total_f4 = nrows * ROW_F4;
    int grid_main = (total_f4 + NT - 1) / NT;        // 30720
    int grid_fix  = (nrows + 255) / 256;             // 256

    prep_kernel<<<1, ROW_F>>>(offset, persistence, diffusion01, dt_seconds,
                              amount01, spread01);
    beat_pulse_main<<<grid_main, NT>>>(history, color_rgb, out, nrows);
    fixup_kernel<<<grid_fix, 256>>>(history, color_rgb, out, nrows);
}